// round 1
// baseline (speedup 1.0000x reference)
#include <cuda_runtime.h>

#define BB 32
#define NN 2048
#define HH 512
#define NCH 8            // n-chunks for the weighted-V pass
#define NPC (NN/NCH)     // 256 rows per chunk
#define MASK_NEG 1e30f

// ---- scratch (device globals; no allocation allowed) ----
__device__ float g_qdot[BB];
__device__ float g_alpha[BB*NN];
__device__ float g_w0[BB*NN];
__device__ float g_w1[BB*NN];
__device__ float g_upart[BB*NCH*2*HH];
__device__ float g_u[BB*2*HH];

__device__ __forceinline__ float warp_sum(float v) {
#pragma unroll
    for (int o = 16; o; o >>= 1) v += __shfl_xor_sync(0xffffffffu, v, o);
    return v;
}
__device__ __forceinline__ float warp_max(float v) {
#pragma unroll
    for (int o = 16; o; o >>= 1) v = fmaxf(v, __shfl_xor_sync(0xffffffffu, v, o));
    return v;
}

// ---------------- kernel 0: qdot[b] = Q[b]·wq + b_att ----------------
__global__ void k_qdot(const float* __restrict__ Q,
                       const float* __restrict__ w_att,
                       const float* __restrict__ b_att) {
    int w = threadIdx.x >> 5, l = threadIdx.x & 31;   // 32 warps, one per b
    const float* q = Q + w * HH;
    float s = 0.f;
#pragma unroll
    for (int i = l; i < HH; i += 32) s += q[i] * w_att[i];
    s = warp_sum(s);
    if (l == 0) g_qdot[w] = s + b_att[0];
}

// ---------------- kernel 1: alpha[b,n] = K[b,n]·wk + qdot[b] - mask ----------------
// one warp per row; 8 warps per block; reads K (128 MB) coalesced via float4
__global__ void k_alpha(const float* __restrict__ K,
                        const float* __restrict__ w_att,
                        const int*   __restrict__ adj) {
    __shared__ float wk[HH];
    for (int i = threadIdx.x; i < HH; i += blockDim.x) wk[i] = w_att[HH + i];
    __syncthreads();
    int w = threadIdx.x >> 5, l = threadIdx.x & 31;
    int r = blockIdx.x * 8 + w;                       // row in [0, B*N)
    const float4* kp = (const float4*)(K + (size_t)r * HH);
    const float4* wp = (const float4*)wk;
    float s = 0.f;
#pragma unroll
    for (int i = 0; i < 4; i++) {                     // 512 floats = 128 float4 / warp
        float4 kv = kp[i * 32 + l];
        float4 wv = wp[i * 32 + l];
        s += kv.x * wv.x + kv.y * wv.y + kv.z * wv.z + kv.w * wv.w;
    }
    s = warp_sum(s);
    if (l == 0) {
        int b = r >> 11;
        g_alpha[r] = s + g_qdot[b] - (1.0f - (float)adj[r]) * MASK_NEG;
    }
}

// ---------------- kernel 2: softmax over N per b; emit attn + premixed weights ----------------
__global__ void k_softmax(const int* __restrict__ s_mask,
                          float* __restrict__ out) {
    __shared__ float red[32];
    int b = blockIdx.x, t = threadIdx.x;              // 1024 threads, 2 elems each
    float a0 = g_alpha[b * NN + t];
    float a1 = g_alpha[b * NN + t + 1024];
    // block max
    float m = warp_max(fmaxf(a0, a1));
    if ((t & 31) == 0) red[t >> 5] = m;
    __syncthreads();
    float bm = red[0];
#pragma unroll
    for (int i = 1; i < 32; i++) bm = fmaxf(bm, red[i]);
    // exp + block sum
    float p0 = __expf(a0 - bm), p1 = __expf(a1 - bm);
    float s = warp_sum(p0 + p1);
    __syncthreads();
    if ((t & 31) == 0) red[t >> 5] = s;
    __syncthreads();
    float tot = 0.f;
#pragma unroll
    for (int i = 0; i < 32; i++) tot += red[i];
    float inv = 1.0f / tot;

    float at0 = p0 * inv, at1 = p1 * inv;
    out[b * NN + t]        = at0;
    out[b * NN + t + 1024] = at1;
    float sm0 = (float)s_mask[b * NN + t];
    float sm1 = (float)s_mask[b * NN + t + 1024];
    g_w0[b * NN + t]        = at0 * sm0;
    g_w1[b * NN + t]        = at0 * (1.0f - sm0);
    g_w0[b * NN + t + 1024] = at1 * sm1;
    g_w1[b * NN + t + 1024] = at1 * (1.0f - sm1);
}

// ---------------- kernel 3: partial weighted V sums (reads V = 128 MB) ----------------
// grid (NCH, B); 512 threads = one h-column each; no atomics -> deterministic
__global__ void k_wv(const float* __restrict__ V) {
    __shared__ float sw0[NPC], sw1[NPC];
    int b = blockIdx.y, c = blockIdx.x;
    int h = threadIdx.x;
    int n0 = c * NPC;
    if (h < NPC) {
        sw0[h] = g_w0[b * NN + n0 + h];
        sw1[h] = g_w1[b * NN + n0 + h];
    }
    __syncthreads();
    const float* vp = V + ((size_t)b * NN + n0) * HH + h;
    float a0 = 0.f, a1 = 0.f;
#pragma unroll 8
    for (int i = 0; i < NPC; i++) {
        float v = __ldg(vp + (size_t)i * HH);
        a0 += sw0[i] * v;
        a1 += sw1[i] * v;
    }
    g_upart[((b * NCH + c) * 2 + 0) * HH + h] = a0;
    g_upart[((b * NCH + c) * 2 + 1) * HH + h] = a1;
}

// ---------------- kernel 3b: reduce partials ----------------
__global__ void k_ured() {
    int b = blockIdx.x, t = threadIdx.x;              // 1024 = 2*512 (j,h)
    float s = 0.f;
#pragma unroll
    for (int c = 0; c < NCH; c++) s += g_upart[(b * NCH + c) * 2 * HH + t];
    g_u[b * 2 * HH + t] = s;
}

// ---------------- kernel 4: attn_sum[b,o] = u0·Wr0[o] + u1·Wr1[o] + Q[b]·Wri[o] ----------------
__global__ void k_out(const float* __restrict__ Q,
                      const float* __restrict__ Wr0,
                      const float* __restrict__ Wr1,
                      const float* __restrict__ Wri,
                      float* __restrict__ out) {
    int b = blockIdx.y;
    int w = threadIdx.x >> 5, l = threadIdx.x & 31;
    int o = blockIdx.x * 8 + w;
    const float* u0 = g_u + b * 2 * HH;
    const float* u1 = u0 + HH;
    const float* q  = Q + b * HH;
    const float* w0 = Wr0 + (size_t)o * HH;
    const float* w1 = Wr1 + (size_t)o * HH;
    const float* wi = Wri + (size_t)o * HH;
    float s = 0.f;
#pragma unroll
    for (int i = l; i < HH; i += 32)
        s += u0[i] * w0[i] + u1[i] * w1[i] + q[i] * wi[i];
    s = warp_sum(s);
    if (l == 0) out[BB * NN + b * HH + o] = s;
}

// ---------------- launch ----------------
extern "C" void kernel_launch(void* const* d_in, const int* in_sizes, int n_in,
                              void* d_out, int out_size) {
    const float* Q     = (const float*)d_in[0];
    const float* K     = (const float*)d_in[1];
    const float* V     = (const float*)d_in[2];
    const int*   adj   = (const int*)d_in[3];
    const int*   smask = (const int*)d_in[4];
    const float* w_att = (const float*)d_in[5];
    const float* b_att = (const float*)d_in[6];
    const float* Wr0   = (const float*)d_in[7];
    const float* Wr1   = (const float*)d_in[8];
    const float* Wri   = (const float*)d_in[9];
    float* out = (float*)d_out;

    k_qdot<<<1, 1024>>>(Q, w_att, b_att);
    k_alpha<<<(BB * NN) / 8, 256>>>(K, w_att, adj);
    k_softmax<<<BB, 1024>>>(smask, out);
    k_wv<<<dim3(NCH, BB), HH>>>(V);
    k_ured<<<BB, 1024>>>();
    k_out<<<dim3(HH / 8, BB), 256>>>(Q, Wr0, Wr1, Wri, out);
}